// round 3
// baseline (speedup 1.0000x reference)
#include <cuda_runtime.h>
#include <cstdint>

#define INV_SCALE 0.35355339059327373f

// Scratch volumes (allocation-free: __device__ globals).
// vol32, vol64: channel-major (C, z, y, x)
// vol128: channel-last (z, y, x, C) for coalesced sampling gathers
__device__ float g_vol32[28 * 32 * 32 * 32];
__device__ float g_vol64[28 * 64 * 64 * 64];
__device__ float g_vol128[128 * 128 * 128 * 28];

// ---------------------------------------------------------------------------
// Inverse 3D Haar butterfly: out(p,q,r) = INV_SCALE * sum_uvw c_uvw (-1)^(up+vq+wr)
// coeff order (u,v,w): c000=approx, c001=aad, c010=ada, c011=add,
//                      c100=daa, c101=dad, c110=dda, c111=ddd
// ---------------------------------------------------------------------------
__device__ __forceinline__ void haar_butterfly(
    float a, float d0, float d1, float d2, float d3, float d4, float d5, float d6,
    float o[2][2][2])
{
    // w-axis (pairs with r)
    float e000 = a  + d0, e001 = a  - d0;
    float e010 = d1 + d2, e011 = d1 - d2;
    float e100 = d3 + d4, e101 = d3 - d4;
    float e110 = d5 + d6, e111 = d5 - d6;
    // v-axis (q)
    float f000 = e000 + e010, f010 = e000 - e010;
    float f001 = e001 + e011, f011 = e001 - e011;
    float f100 = e100 + e110, f110 = e100 - e110;
    float f101 = e101 + e111, f111 = e101 - e111;
    // u-axis (p)
    o[0][0][0] = (f000 + f100) * INV_SCALE;
    o[0][0][1] = (f001 + f101) * INV_SCALE;
    o[0][1][0] = (f010 + f110) * INV_SCALE;
    o[0][1][1] = (f011 + f111) * INV_SCALE;
    o[1][0][0] = (f000 - f100) * INV_SCALE;
    o[1][0][1] = (f001 - f101) * INV_SCALE;
    o[1][1][0] = (f010 - f110) * INV_SCALE;
    o[1][1][1] = (f011 - f111) * INV_SCALE;
}

// ---------------------------------------------------------------------------
// Levels 0 and 1: channel-major in, channel-major out. One thread per coarse
// voxel per channel; reads coalesced along k, writes as float2 (coalesced).
// ---------------------------------------------------------------------------
template <int D>
__global__ void idwt_cm_kernel(const float* __restrict__ approx,
                               const float* __restrict__ det,
                               float* __restrict__ out)
{
    const int D3 = D * D * D;
    int tid = blockIdx.x * blockDim.x + threadIdx.x;
    if (tid >= 28 * D3) return;

    int k = tid % D;
    int j = (tid / D) % D;
    int i = (tid / (D * D)) % D;
    int c = tid / D3;
    int sp = (i * D + j) * D + k;

    float a  = __ldg(&approx[c * D3 + sp]);
    float d0 = __ldg(&det[(0 * 28 + c) * D3 + sp]);
    float d1 = __ldg(&det[(1 * 28 + c) * D3 + sp]);
    float d2 = __ldg(&det[(2 * 28 + c) * D3 + sp]);
    float d3 = __ldg(&det[(3 * 28 + c) * D3 + sp]);
    float d4 = __ldg(&det[(4 * 28 + c) * D3 + sp]);
    float d5 = __ldg(&det[(5 * 28 + c) * D3 + sp]);
    float d6 = __ldg(&det[(6 * 28 + c) * D3 + sp]);

    float o[2][2][2];
    haar_butterfly(a, d0, d1, d2, d3, d4, d5, d6, o);

    const int E = 2 * D;
#pragma unroll
    for (int p = 0; p < 2; ++p)
#pragma unroll
        for (int q = 0; q < 2; ++q) {
            int base = ((c * E + (2 * i + p)) * E + (2 * j + q)) * E + 2 * k;
            float2 v = make_float2(o[p][q][0], o[p][q][1]);
            *reinterpret_cast<float2*>(&out[base]) = v;
        }
}

// ---------------------------------------------------------------------------
// Level 2: channel-major 64^3 in -> channel-LAST 128^3 out, transposed through
// shared memory. One block per (i,j) coarse row. 896 threads = 28 c * 32 k.
// smem rows padded to stride 29 (2-way bank conflict max on stores,
// conflict-free on the streaming read-out).
// ---------------------------------------------------------------------------
__global__ __launch_bounds__(896) void idwt2_kernel(const float* __restrict__ det)
{
    const int D = 64, D3 = D * D * D;
    int ij = blockIdx.x;
    int i = ij / 64;
    int j = ij % 64;
    int c  = threadIdx.x / 32;   // 0..27
    int kl = threadIdx.x % 32;   // 0..31

    __shared__ float sm[4][64 * 29];

    for (int h = 0; h < 2; ++h) {
        int k  = kl + 32 * h;
        int sp = (i * D + j) * D + k;

        float a  = __ldg(&g_vol64[c * D3 + sp]);
        float d0 = __ldg(&det[(0 * 28 + c) * D3 + sp]);
        float d1 = __ldg(&det[(1 * 28 + c) * D3 + sp]);
        float d2 = __ldg(&det[(2 * 28 + c) * D3 + sp]);
        float d3 = __ldg(&det[(3 * 28 + c) * D3 + sp]);
        float d4 = __ldg(&det[(4 * 28 + c) * D3 + sp]);
        float d5 = __ldg(&det[(5 * 28 + c) * D3 + sp]);
        float d6 = __ldg(&det[(6 * 28 + c) * D3 + sp]);

        float o[2][2][2];
        haar_butterfly(a, d0, d1, d2, d3, d4, d5, d6, o);

#pragma unroll
        for (int p = 0; p < 2; ++p)
#pragma unroll
            for (int q = 0; q < 2; ++q)
#pragma unroll
                for (int r = 0; r < 2; ++r)
                    sm[p * 2 + q][(2 * kl + r) * 29 + c] = o[p][q][r];

        __syncthreads();

        // stream out: per (p,q), a contiguous run of 64*28 floats
        for (int idx = threadIdx.x; idx < 4 * 64 * 28; idx += 896) {
            int pq  = idx / (64 * 28);
            int rem = idx % (64 * 28);
            int x   = rem / 28;
            int cc  = rem % 28;
            int p = pq >> 1, q = pq & 1;
            int base = (((2 * i + p) * 128 + (2 * j + q)) * 128 + 64 * h) * 28;
            g_vol128[base + rem] = sm[pq][x * 29 + cc];
        }
        __syncthreads();
    }
}

// ---------------------------------------------------------------------------
// Sampling: one warp per point, lane = channel (28 active lanes).
// Each corner gather is a coalesced ~112B transaction.
// ---------------------------------------------------------------------------
__global__ void sample_kernel(const float* __restrict__ xyz,
                              float* __restrict__ out, int n)
{
    int w    = (blockIdx.x * blockDim.x + threadIdx.x) >> 5;
    int lane = threadIdx.x & 31;
    if (w >= n) return;

    float x = __ldg(&xyz[3 * w + 0]);
    float y = __ldg(&xyz[3 * w + 1]);
    float z = __ldg(&xyz[3 * w + 2]);

    const float R1 = 127.0f;
    float px = (x / 1.5f + 1.0f) * 0.5f * R1;
    float py = (y / 1.5f + 1.0f) * 0.5f * R1;
    float pz = (z / 1.5f + 1.0f) * 0.5f * R1;

    float flx = floorf(px), fly = floorf(py), flz = floorf(pz);
    int x0 = (int)flx, y0 = (int)fly, z0 = (int)flz;
    float fx = px - flx, fy = py - fly, fz = pz - flz;

    float wx[2] = {1.0f - fx, fx};
    float wy[2] = {1.0f - fy, fy};
    float wz[2] = {1.0f - fz, fz};

    float acc = 0.0f;
    int c = lane;
    bool active = (lane < 28);

#pragma unroll
    for (int dz = 0; dz < 2; ++dz) {
        int iz = z0 + dz;
        bool vz = (iz >= 0) & (iz < 128);
#pragma unroll
        for (int dy = 0; dy < 2; ++dy) {
            int iy = y0 + dy;
            bool vy = (iy >= 0) & (iy < 128);
#pragma unroll
            for (int dx = 0; dx < 2; ++dx) {
                int ix = x0 + dx;
                bool vx = (ix >= 0) & (ix < 128);
                if (active & vx & vy & vz) {
                    float wgt = wx[dx] * wy[dy] * wz[dz];
                    int addr = ((iz * 128 + iy) * 128 + ix) * 28 + c;
                    acc += wgt * __ldg(&g_vol128[addr]);
                }
            }
        }
    }

    if (active) out[(size_t)w * 28 + lane] = acc;
}

// ---------------------------------------------------------------------------
extern "C" void kernel_launch(void* const* d_in, const int* in_sizes, int n_in,
                              void* d_out, int out_size)
{
    const float* approx    = (const float*)d_in[0]; // (28,16,16,16)
    const float* details_0 = (const float*)d_in[1]; // (7,28,16^3)
    const float* details_1 = (const float*)d_in[2]; // (7,28,32^3)
    const float* details_2 = (const float*)d_in[3]; // (7,28,64^3)
    const float* xyz       = (const float*)d_in[4]; // (N,3)
    float* out             = (float*)d_out;         // (N,28)

    int n = in_sizes[4] / 3;

    float* p32  = nullptr;
    float* p64  = nullptr;
    cudaGetSymbolAddress((void**)&p32, g_vol32);
    cudaGetSymbolAddress((void**)&p64, g_vol64);

    // Level 0: 16 -> 32 (channel-major)
    {
        int nthreads = 28 * 16 * 16 * 16;
        idwt_cm_kernel<16><<<(nthreads + 255) / 256, 256>>>(approx, details_0, p32);
    }
    // Level 1: 32 -> 64 (channel-major)
    {
        int nthreads = 28 * 32 * 32 * 32;
        idwt_cm_kernel<32><<<(nthreads + 255) / 256, 256>>>(p32, details_1, p64);
    }
    // Level 2: 64 -> 128, transposed to channel-last
    idwt2_kernel<<<64 * 64, 896>>>(details_2);

    // Sampling: warp per point
    {
        long long threads = (long long)n * 32;
        int blocks = (int)((threads + 255) / 256);
        sample_kernel<<<blocks, 256>>>(xyz, out, n);
    }
}

// round 5
// speedup vs baseline: 1.6515x; 1.6515x over previous
#include <cuda_runtime.h>
#include <cuda_fp16.h>
#include <cstdint>

#define INV_SCALE 0.35355339059327373f

// Scratch volumes (allocation-free: __device__ globals).
// vol32, vol64: channel-major (C, z, y, x), fp32
// vol128h: channel-last (z, y, x, C) in fp16 -> 117MB, fits in L2
__device__ float  g_vol32[28 * 32 * 32 * 32];
__device__ float  g_vol64[28 * 64 * 64 * 64];
__device__ __half g_vol128h[128 * 128 * 128 * 28];

// ---------------------------------------------------------------------------
// Inverse 3D Haar butterfly
// ---------------------------------------------------------------------------
__device__ __forceinline__ void haar_butterfly(
    float a, float d0, float d1, float d2, float d3, float d4, float d5, float d6,
    float o[2][2][2])
{
    float e000 = a  + d0, e001 = a  - d0;
    float e010 = d1 + d2, e011 = d1 - d2;
    float e100 = d3 + d4, e101 = d3 - d4;
    float e110 = d5 + d6, e111 = d5 - d6;
    float f000 = e000 + e010, f010 = e000 - e010;
    float f001 = e001 + e011, f011 = e001 - e011;
    float f100 = e100 + e110, f110 = e100 - e110;
    float f101 = e101 + e111, f111 = e101 - e111;
    o[0][0][0] = (f000 + f100) * INV_SCALE;
    o[0][0][1] = (f001 + f101) * INV_SCALE;
    o[0][1][0] = (f010 + f110) * INV_SCALE;
    o[0][1][1] = (f011 + f111) * INV_SCALE;
    o[1][0][0] = (f000 - f100) * INV_SCALE;
    o[1][0][1] = (f001 - f101) * INV_SCALE;
    o[1][1][0] = (f010 - f110) * INV_SCALE;
    o[1][1][1] = (f011 - f111) * INV_SCALE;
}

// ---------------------------------------------------------------------------
// Levels 0 and 1: channel-major in/out, fp32.
// ---------------------------------------------------------------------------
template <int D>
__global__ void idwt_cm_kernel(const float* __restrict__ approx,
                               const float* __restrict__ det,
                               float* __restrict__ out)
{
    const int D3 = D * D * D;
    int tid = blockIdx.x * blockDim.x + threadIdx.x;
    if (tid >= 28 * D3) return;

    int k = tid % D;
    int j = (tid / D) % D;
    int i = (tid / (D * D)) % D;
    int c = tid / D3;
    int sp = (i * D + j) * D + k;

    float a  = __ldg(&approx[c * D3 + sp]);
    float d0 = __ldg(&det[(0 * 28 + c) * D3 + sp]);
    float d1 = __ldg(&det[(1 * 28 + c) * D3 + sp]);
    float d2 = __ldg(&det[(2 * 28 + c) * D3 + sp]);
    float d3 = __ldg(&det[(3 * 28 + c) * D3 + sp]);
    float d4 = __ldg(&det[(4 * 28 + c) * D3 + sp]);
    float d5 = __ldg(&det[(5 * 28 + c) * D3 + sp]);
    float d6 = __ldg(&det[(6 * 28 + c) * D3 + sp]);

    float o[2][2][2];
    haar_butterfly(a, d0, d1, d2, d3, d4, d5, d6, o);

    const int E = 2 * D;
#pragma unroll
    for (int p = 0; p < 2; ++p)
#pragma unroll
        for (int q = 0; q < 2; ++q) {
            int base = ((c * E + (2 * i + p)) * E + (2 * j + q)) * E + 2 * k;
            float2 v = make_float2(o[p][q][0], o[p][q][1]);
            *reinterpret_cast<float2*>(&out[base]) = v;
        }
}

// ---------------------------------------------------------------------------
// Level 2: channel-major 64^3 fp32 in -> channel-LAST 128^3 fp16 out,
// transposed through shared memory. One block per (i,j) coarse row.
// Streaming reads (__ldcs) so the fp16 volume stays L2-resident.
// ---------------------------------------------------------------------------
__global__ __launch_bounds__(896) void idwt2_kernel(const float* __restrict__ det)
{
    const int D = 64, D3 = D * D * D;
    int ij = blockIdx.x;
    int i = ij / 64;
    int j = ij % 64;
    int c  = threadIdx.x / 32;   // 0..27
    int kl = threadIdx.x % 32;   // 0..31

    __shared__ float sm[4][64 * 29];

    for (int h = 0; h < 2; ++h) {
        int k  = kl + 32 * h;
        int sp = (i * D + j) * D + k;

        float a  = __ldcs(&g_vol64[c * D3 + sp]);
        float d0 = __ldcs(&det[(0 * 28 + c) * D3 + sp]);
        float d1 = __ldcs(&det[(1 * 28 + c) * D3 + sp]);
        float d2 = __ldcs(&det[(2 * 28 + c) * D3 + sp]);
        float d3 = __ldcs(&det[(3 * 28 + c) * D3 + sp]);
        float d4 = __ldcs(&det[(4 * 28 + c) * D3 + sp]);
        float d5 = __ldcs(&det[(5 * 28 + c) * D3 + sp]);
        float d6 = __ldcs(&det[(6 * 28 + c) * D3 + sp]);

        float o[2][2][2];
        haar_butterfly(a, d0, d1, d2, d3, d4, d5, d6, o);

#pragma unroll
        for (int p = 0; p < 2; ++p)
#pragma unroll
            for (int q = 0; q < 2; ++q)
#pragma unroll
                for (int r = 0; r < 2; ++r)
                    sm[p * 2 + q][(2 * kl + r) * 29 + c] = o[p][q][r];

        __syncthreads();

        // stream out as half2: per (p,q), contiguous run of 64*28 halfs
        __half2* vol2 = reinterpret_cast<__half2*>(g_vol128h);
        for (int idx = threadIdx.x; idx < 4 * 64 * 14; idx += 896) {
            int pq   = idx / (64 * 14);
            int rem2 = idx % (64 * 14);
            int x    = rem2 / 14;
            int m    = rem2 % 14;
            int p = pq >> 1, q = pq & 1;
            float lo = sm[pq][x * 29 + 2 * m];
            float hi = sm[pq][x * 29 + 2 * m + 1];
            // half2 index: (((2i+p)*128 + (2j+q))*128 + 64h)*14 + rem2
            int base2 = ((((2 * i + p) * 128 + (2 * j + q)) * 128 + 64 * h) * 14);
            vol2[base2 + rem2] = __floats2half2_rn(lo, hi);
        }
        __syncthreads();
    }
}

// ---------------------------------------------------------------------------
// Sampling: 2 points per warp (one per half-warp), lane handles a channel
// PAIR via half2 loads. 14 active lanes per half-warp. Output via __stwt
// (write-through) so the L2-resident volume isn't evicted.
// ---------------------------------------------------------------------------
__global__ void sample_kernel(const float* __restrict__ xyz,
                              float* __restrict__ out, int n)
{
    int warp   = (blockIdx.x * blockDim.x + threadIdx.x) >> 5;
    int lane   = threadIdx.x & 31;
    int sub    = lane >> 4;        // which point within the warp
    int lane14 = lane & 15;        // channel-pair index
    int p      = warp * 2 + sub;
    if (p >= n || lane14 >= 14) return;

    float x = __ldcs(&xyz[3 * p + 0]);
    float y = __ldcs(&xyz[3 * p + 1]);
    float z = __ldcs(&xyz[3 * p + 2]);

    // (x/1.5 + 1) * 0.5 * 127
    const float S = 127.0f / 3.0f;
    float px = fmaf(x, S, 63.5f);
    float py = fmaf(y, S, 63.5f);
    float pz = fmaf(z, S, 63.5f);

    float flx = floorf(px), fly = floorf(py), flz = floorf(pz);
    int x0 = (int)flx, y0 = (int)fly, z0 = (int)flz;
    float fx = px - flx, fy = py - fly, fz = pz - flz;

    float wx[2] = {1.0f - fx, fx};
    float wy[2] = {1.0f - fy, fy};
    float wz[2] = {1.0f - fz, fz};

    const __half2* __restrict__ vol2 =
        reinterpret_cast<const __half2*>(g_vol128h);

    float accx = 0.0f, accy = 0.0f;

#pragma unroll
    for (int dz = 0; dz < 2; ++dz) {
        int iz = z0 + dz;
        bool vz = (iz >= 0) & (iz < 128);
#pragma unroll
        for (int dy = 0; dy < 2; ++dy) {
            int iy = y0 + dy;
            bool vy = (iy >= 0) & (iy < 128);
#pragma unroll
            for (int dx = 0; dx < 2; ++dx) {
                int ix = x0 + dx;
                bool vx = (ix >= 0) & (ix < 128);
                if (vx & vy & vz) {
                    float wgt = wx[dx] * wy[dy] * wz[dz];
                    int idx = ((iz * 128 + iy) * 128 + ix) * 14 + lane14;
                    float2 f = __half22float2(vol2[idx]);
                    accx = fmaf(wgt, f.x, accx);
                    accy = fmaf(wgt, f.y, accy);
                }
            }
        }
    }

    __stwt(reinterpret_cast<float2*>(&out[(size_t)p * 28 + 2 * lane14]),
           make_float2(accx, accy));
}

// ---------------------------------------------------------------------------
extern "C" void kernel_launch(void* const* d_in, const int* in_sizes, int n_in,
                              void* d_out, int out_size)
{
    const float* approx    = (const float*)d_in[0]; // (28,16,16,16)
    const float* details_0 = (const float*)d_in[1]; // (7,28,16^3)
    const float* details_1 = (const float*)d_in[2]; // (7,28,32^3)
    const float* details_2 = (const float*)d_in[3]; // (7,28,64^3)
    const float* xyz       = (const float*)d_in[4]; // (N,3)
    float* out             = (float*)d_out;         // (N,28)

    int n = in_sizes[4] / 3;

    float* p32 = nullptr;
    float* p64 = nullptr;
    cudaGetSymbolAddress((void**)&p32, g_vol32);
    cudaGetSymbolAddress((void**)&p64, g_vol64);

    // Level 0: 16 -> 32 (channel-major fp32)
    {
        int nthreads = 28 * 16 * 16 * 16;
        idwt_cm_kernel<16><<<(nthreads + 255) / 256, 256>>>(approx, details_0, p32);
    }
    // Level 1: 32 -> 64 (channel-major fp32)
    {
        int nthreads = 28 * 32 * 32 * 32;
        idwt_cm_kernel<32><<<(nthreads + 255) / 256, 256>>>(p32, details_1, p64);
    }
    // Level 2: 64 -> 128, transposed to channel-last fp16
    idwt2_kernel<<<64 * 64, 896>>>(details_2);

    // Sampling: 2 points per warp, 16 points per 256-thread block
    {
        int blocks = (n + 15) / 16;
        sample_kernel<<<blocks, 256>>>(xyz, out, n);
    }
}